// round 1
// baseline (speedup 1.0000x reference)
#include <cuda_runtime.h>

// ---------------------------------------------------------------------------
// GIN GNN, 5 layers, D=300, N=100000 nodes, E=200000 edges. Full fp32.
// Pipeline per layer:
//   agg = h + c_l (self loop, fused into previous BN-apply / embed kernel)
//   scatter: agg[dst] += h[src] + ee1[l][a0] + ee2[l][a1]   (atomic v4)
//   h1 = relu(agg @ W1 + b1)          [N,600]  SGEMM
//   h2 = h1 @ W2 + b2                 [N,300]  SGEMM
//   batchnorm (batch stats), relu (except last), write h (+ next agg init)
// ---------------------------------------------------------------------------

#define DD   300
#define DD4  75
#define NL   5

__device__ __align__(16) float g_h  [100000 * 300];
__device__ __align__(16) float g_agg[100000 * 300];
__device__ __align__(16) float g_h1 [100000 * 600];
__device__ __align__(16) float g_h2 [100000 * 300];
__device__ __align__(16) float g_stat[600];   // [0:300) sum, [300:600) sumsq
__device__ __align__(16) float g_bnA[300];
__device__ __align__(16) float g_bnB[300];

// ---------------------------------------------------------------------------
// Embedding + layer-0 agg init:  h = xemb1[x0] + xemb2[x1];  agg = h + c0
// ---------------------------------------------------------------------------
__global__ void k_embed_init(const int* __restrict__ x,
                             const float4* __restrict__ e1,
                             const float4* __restrict__ e2,
                             const float4* __restrict__ c1,
                             const float4* __restrict__ c2,
                             int n)
{
    int idx = blockIdx.x * blockDim.x + threadIdx.x;
    if (idx >= n * DD4) return;
    int i = idx / DD4;
    int j = idx - i * DD4;
    int a0 = x[2 * i];
    int a1 = x[2 * i + 1];
    float4 v1 = e1[a0 * DD4 + j];
    float4 v2 = e2[a1 * DD4 + j];
    float4 h = make_float4(v1.x + v2.x, v1.y + v2.y, v1.z + v2.z, v1.w + v2.w);
    reinterpret_cast<float4*>(g_h)[idx] = h;
    float4 cc1 = c1[j];
    float4 cc2 = c2[j];
    reinterpret_cast<float4*>(g_agg)[idx] =
        make_float4(h.x + cc1.x + cc2.x, h.y + cc1.y + cc2.y,
                    h.z + cc1.z + cc2.z, h.w + cc1.w + cc2.w);
}

// ---------------------------------------------------------------------------
// Edge scatter: one warp per edge, vectorized atomic add (red.global.v4.f32)
// ---------------------------------------------------------------------------
__global__ void k_scatter(const int* __restrict__ ei,
                          const int* __restrict__ ea,
                          const float* __restrict__ ee1,
                          const float* __restrict__ ee2,
                          int E)
{
    int gw   = (blockIdx.x * blockDim.x + threadIdx.x) >> 5;
    int lane = threadIdx.x & 31;
    if (gw >= E) return;
    int src = ei[gw];
    int dst = ei[E + gw];
    int a0  = ea[2 * gw];
    int a1  = ea[2 * gw + 1];
    const float4* hs = reinterpret_cast<const float4*>(g_h) + (size_t)src * DD4;
    const float4* t1 = reinterpret_cast<const float4*>(ee1) + a0 * DD4;
    const float4* t2 = reinterpret_cast<const float4*>(ee2) + a1 * DD4;
    float4*       ag = reinterpret_cast<float4*>(g_agg) + (size_t)dst * DD4;
    for (int i = lane; i < DD4; i += 32) {
        float4 v = hs[i];
        float4 w1 = t1[i];
        float4 w2 = t2[i];
        float4 m = make_float4(v.x + w1.x + w2.x, v.y + w1.y + w2.y,
                               v.z + w1.z + w2.z, v.w + w1.w + w2.w);
        asm volatile("red.global.add.v4.f32 [%0], {%1,%2,%3,%4};"
                     :: "l"(ag + i), "f"(m.x), "f"(m.y), "f"(m.z), "f"(m.w)
                     : "memory");
    }
}

// ---------------------------------------------------------------------------
// SGEMM: C[M,N] = A[M,K] @ B[K,N] + bias, optional ReLU.
// 128x128 block tile, BK=8, 8x8 per-thread micro-tile, 256 threads.
// ---------------------------------------------------------------------------
#define BM 128
#define BN 128
#define BK 8
#define TM 8
#define TN 8

__global__ void __launch_bounds__(256)
k_sgemm(const float* __restrict__ A, const float* __restrict__ B,
        const float* __restrict__ bias, float* __restrict__ C,
        int M, int N, int K, int doRelu)
{
    __shared__ float As[BK][BM];
    __shared__ float Bs[BK][BN];

    const int tid     = threadIdx.x;
    const int rowBase = blockIdx.y * BM;
    const int colBase = blockIdx.x * BN;

    // A tile load mapping: 128 rows x 8 cols = 256 float4
    const int aRow = tid >> 1;          // 0..127
    const int aCol = (tid & 1) * 4;     // 0 or 4
    // B tile load mapping: 8 rows x 128 cols = 256 float4
    const int bRow = tid >> 5;          // 0..7
    const int bCol = (tid & 31) * 4;    // 0..124

    const int tx = tid & 15;            // 0..15
    const int ty = tid >> 4;            // 0..15

    float acc[TM][TN];
#pragma unroll
    for (int i = 0; i < TM; i++)
#pragma unroll
        for (int j = 0; j < TN; j++) acc[i][j] = 0.0f;

    float ra[TM], rb[TN];

    for (int k0 = 0; k0 < K; k0 += BK) {
        // load A tile (transposed into As[k][m])
        float4 av = make_float4(0.f, 0.f, 0.f, 0.f);
        {
            int gr = rowBase + aRow;
            int gc = k0 + aCol;
            if (gr < M && gc < K)
                av = *reinterpret_cast<const float4*>(A + (size_t)gr * K + gc);
        }
        As[aCol + 0][aRow] = av.x;
        As[aCol + 1][aRow] = av.y;
        As[aCol + 2][aRow] = av.z;
        As[aCol + 3][aRow] = av.w;
        // load B tile
        float4 bv = make_float4(0.f, 0.f, 0.f, 0.f);
        {
            int gk = k0 + bRow;
            int gn = colBase + bCol;
            if (gk < K && gn < N)
                bv = *reinterpret_cast<const float4*>(B + (size_t)gk * N + gn);
        }
        *reinterpret_cast<float4*>(&Bs[bRow][bCol]) = bv;
        __syncthreads();

#pragma unroll
        for (int k = 0; k < BK; k++) {
            *reinterpret_cast<float4*>(&ra[0]) = *reinterpret_cast<float4*>(&As[k][ty * TM]);
            *reinterpret_cast<float4*>(&ra[4]) = *reinterpret_cast<float4*>(&As[k][ty * TM + 4]);
            *reinterpret_cast<float4*>(&rb[0]) = *reinterpret_cast<float4*>(&Bs[k][tx * TN]);
            *reinterpret_cast<float4*>(&rb[4]) = *reinterpret_cast<float4*>(&Bs[k][tx * TN + 4]);
#pragma unroll
            for (int i = 0; i < TM; i++)
#pragma unroll
                for (int j = 0; j < TN; j++)
                    acc[i][j] = fmaf(ra[i], rb[j], acc[i][j]);
        }
        __syncthreads();
    }

    // epilogue: bias + optional relu
#pragma unroll
    for (int i = 0; i < TM; i++) {
        int r = rowBase + ty * TM + i;
        if (r >= M) continue;
#pragma unroll
        for (int j = 0; j < TN; j += 4) {
            int c = colBase + tx * TN + j;
            if (c >= N) continue;            // N % 4 == 0, float4 granularity
            float4 o;
            o.x = acc[i][j + 0] + bias[c + 0];
            o.y = acc[i][j + 1] + bias[c + 1];
            o.z = acc[i][j + 2] + bias[c + 2];
            o.w = acc[i][j + 3] + bias[c + 3];
            if (doRelu) {
                o.x = fmaxf(o.x, 0.f); o.y = fmaxf(o.y, 0.f);
                o.z = fmaxf(o.z, 0.f); o.w = fmaxf(o.w, 0.f);
            }
            *reinterpret_cast<float4*>(C + (size_t)r * N + c) = o;
        }
    }
}

// ---------------------------------------------------------------------------
// BatchNorm: stats (per-channel sum & sumsq), finalize, apply (+ next agg init)
// ---------------------------------------------------------------------------
__global__ void k_zero600()
{
    int i = threadIdx.x;
    if (i < 600) g_stat[i] = 0.0f;
}

__global__ void k_bnstats(int n)
{
    int c = threadIdx.x;             // blockDim.x = 320, active c < 300
    if (c >= DD) return;
    int r0 = blockIdx.x * 128;
    int r1 = r0 + 128;
    if (r1 > n) r1 = n;
    float s = 0.f, q = 0.f;
    for (int r = r0; r < r1; r++) {
        float v = g_h2[(size_t)r * DD + c];
        s += v;
        q += v * v;
    }
    atomicAdd(&g_stat[c], s);
    atomicAdd(&g_stat[DD + c], q);
}

__global__ void k_bnfin(const float* __restrict__ gamma,
                        const float* __restrict__ beta, float invn)
{
    int c = threadIdx.x;
    if (c >= DD) return;
    float mean = g_stat[c] * invn;
    float var  = g_stat[DD + c] * invn - mean * mean;
    float a = gamma[c] * rsqrtf(var + 1e-5f);
    g_bnA[c] = a;
    g_bnB[c] = beta[c] - mean * a;
}

__global__ void k_bnapply(float4* __restrict__ outH,
                          float4* __restrict__ outAgg,
                          const float4* __restrict__ c1,
                          const float4* __restrict__ c2,
                          int n, int doRelu)
{
    int idx = blockIdx.x * blockDim.x + threadIdx.x;
    if (idx >= n * DD4) return;
    int j = idx % DD4;
    float4 v = reinterpret_cast<const float4*>(g_h2)[idx];
    float4 A = reinterpret_cast<const float4*>(g_bnA)[j];
    float4 B = reinterpret_cast<const float4*>(g_bnB)[j];
    float4 o = make_float4(fmaf(A.x, v.x, B.x), fmaf(A.y, v.y, B.y),
                           fmaf(A.z, v.z, B.z), fmaf(A.w, v.w, B.w));
    if (doRelu) {
        o.x = fmaxf(o.x, 0.f); o.y = fmaxf(o.y, 0.f);
        o.z = fmaxf(o.z, 0.f); o.w = fmaxf(o.w, 0.f);
    }
    outH[idx] = o;
    if (outAgg != nullptr) {
        float4 cc1 = c1[j];
        float4 cc2 = c2[j];
        outAgg[idx] = make_float4(o.x + cc1.x + cc2.x, o.y + cc1.y + cc2.y,
                                  o.z + cc1.z + cc2.z, o.w + cc1.w + cc2.w);
    }
}

// ---------------------------------------------------------------------------
// Host launcher
// ---------------------------------------------------------------------------
extern "C" void kernel_launch(void* const* d_in, const int* in_sizes, int n_in,
                              void* d_out, int out_size)
{
    const int*   x     = (const int*)  d_in[0];   // [N,2]
    const int*   ei    = (const int*)  d_in[1];   // [2,E]
    const int*   ea    = (const int*)  d_in[2];   // [E,2]
    const float* xe1   = (const float*)d_in[3];   // [121,300]
    const float* xe2   = (const float*)d_in[4];   // [11,300]
    const float* ee1   = (const float*)d_in[5];   // [5,7,300]
    const float* ee2   = (const float*)d_in[6];   // [5,3,300]
    const float* w1    = (const float*)d_in[7];   // [5,300,600]
    const float* b1    = (const float*)d_in[8];   // [5,600]
    const float* w2    = (const float*)d_in[9];   // [5,600,300]
    const float* b2    = (const float*)d_in[10];  // [5,300]
    const float* gamma = (const float*)d_in[11];  // [5,300]
    const float* beta  = (const float*)d_in[12];  // [5,300]

    const int N = in_sizes[0] / 2;
    const int E = in_sizes[1] / 2;

    float *h, *agg, *h1, *h2;
    cudaGetSymbolAddress((void**)&h,   g_h);
    cudaGetSymbolAddress((void**)&agg, g_agg);
    cudaGetSymbolAddress((void**)&h1,  g_h1);
    cudaGetSymbolAddress((void**)&h2,  g_h2);

    const int ewBlocks = (N * DD4 + 255) / 256;   // elementwise grid
    const int scBlocks = (E * 32 + 255) / 256;    // warp-per-edge grid

    // embed + layer-0 agg init (self-loop edge emb: ea0=4, ea1=0)
    k_embed_init<<<ewBlocks, 256>>>(
        x,
        (const float4*)xe1, (const float4*)xe2,
        (const float4*)(ee1 + 4 * DD),   // edge_emb1[0][4]
        (const float4*)(ee2),            // edge_emb2[0][0]
        N);

    for (int l = 0; l < NL; l++) {
        const float* ee1l = ee1 + (size_t)l * 7 * DD;
        const float* ee2l = ee2 + (size_t)l * 3 * DD;

        k_scatter<<<scBlocks, 256>>>(ei, ea, ee1l, ee2l, E);

        // h1 = relu(agg @ W1 + b1)   [N,600]
        {
            dim3 grid((600 + BN - 1) / BN, (N + BM - 1) / BM);
            k_sgemm<<<grid, 256>>>(agg, w1 + (size_t)l * DD * 600,
                                   b1 + (size_t)l * 600, h1,
                                   N, 600, DD, 1);
        }

        k_zero600<<<1, 640>>>();

        // h2 = h1 @ W2 + b2          [N,300]
        {
            dim3 grid((DD + BN - 1) / BN, (N + BM - 1) / BM);
            k_sgemm<<<grid, 256>>>(h1, w2 + (size_t)l * 600 * DD,
                                   b2 + (size_t)l * DD, h2,
                                   N, DD, 600, 0);
        }

        k_bnstats<<<(N + 127) / 128, 320>>>(N);
        k_bnfin<<<1, 320>>>(gamma + (size_t)l * DD, beta + (size_t)l * DD,
                            1.0f / (float)N);

        const bool last = (l == NL - 1);
        const float* ce1 = last ? ee1 : (ee1 + (size_t)(l + 1) * 7 * DD + 4 * DD);
        const float* ce2 = last ? ee2 : (ee2 + (size_t)(l + 1) * 3 * DD);
        k_bnapply<<<ewBlocks, 256>>>(
            last ? (float4*)d_out : (float4*)h,
            last ? (float4*)nullptr : (float4*)agg,
            (const float4*)ce1, (const float4*)ce2,
            N, last ? 0 : 1);
    }
}

// round 2
// speedup vs baseline: 1.0003x; 1.0003x over previous
#include <cuda_runtime.h>

// ---------------------------------------------------------------------------
// GIN GNN, 5 layers, D=300, N=100000 nodes, E=200000 edges. Full fp32.
// Pipeline per layer:
//   agg = h + c_l (self loop, fused into previous BN-apply / embed kernel)
//   scatter: agg[dst] += h[src] + ee1[l][a0] + ee2[l][a1]   (atomic v4)
//   h1 = relu(agg @ W1 + b1)          [N,600]  SGEMM
//   h2 = h1 @ W2 + b2                 [N,300]  SGEMM
//   batchnorm (batch stats), relu (except last), write h (+ next agg init)
// ---------------------------------------------------------------------------

#define DD   300
#define DD4  75
#define NL   5

__device__ __align__(16) float g_h  [100000 * 300];
__device__ __align__(16) float g_agg[100000 * 300];
__device__ __align__(16) float g_h1 [100000 * 600];
__device__ __align__(16) float g_h2 [100000 * 300];
__device__ __align__(16) float g_stat[600];   // [0:300) sum, [300:600) sumsq
__device__ __align__(16) float g_bnA[300];
__device__ __align__(16) float g_bnB[300];

// ---------------------------------------------------------------------------
// Embedding + layer-0 agg init:  h = xemb1[x0] + xemb2[x1];  agg = h + c0
// ---------------------------------------------------------------------------
__global__ void k_embed_init(const int* __restrict__ x,
                             const float4* __restrict__ e1,
                             const float4* __restrict__ e2,
                             const float4* __restrict__ c1,
                             const float4* __restrict__ c2,
                             int n)
{
    int idx = blockIdx.x * blockDim.x + threadIdx.x;
    if (idx >= n * DD4) return;
    int i = idx / DD4;
    int j = idx - i * DD4;
    int a0 = x[2 * i];
    int a1 = x[2 * i + 1];
    float4 v1 = e1[a0 * DD4 + j];
    float4 v2 = e2[a1 * DD4 + j];
    float4 h = make_float4(v1.x + v2.x, v1.y + v2.y, v1.z + v2.z, v1.w + v2.w);
    reinterpret_cast<float4*>(g_h)[idx] = h;
    float4 cc1 = c1[j];
    float4 cc2 = c2[j];
    reinterpret_cast<float4*>(g_agg)[idx] =
        make_float4(h.x + cc1.x + cc2.x, h.y + cc1.y + cc2.y,
                    h.z + cc1.z + cc2.z, h.w + cc1.w + cc2.w);
}

// ---------------------------------------------------------------------------
// Edge scatter: one warp per edge, vectorized atomic add (red.global.v4.f32)
// ---------------------------------------------------------------------------
__global__ void k_scatter(const int* __restrict__ ei,
                          const int* __restrict__ ea,
                          const float* __restrict__ ee1,
                          const float* __restrict__ ee2,
                          int E)
{
    int gw   = (blockIdx.x * blockDim.x + threadIdx.x) >> 5;
    int lane = threadIdx.x & 31;
    if (gw >= E) return;
    int src = ei[gw];
    int dst = ei[E + gw];
    int a0  = ea[2 * gw];
    int a1  = ea[2 * gw + 1];
    const float4* hs = reinterpret_cast<const float4*>(g_h) + (size_t)src * DD4;
    const float4* t1 = reinterpret_cast<const float4*>(ee1) + a0 * DD4;
    const float4* t2 = reinterpret_cast<const float4*>(ee2) + a1 * DD4;
    float4*       ag = reinterpret_cast<float4*>(g_agg) + (size_t)dst * DD4;
    for (int i = lane; i < DD4; i += 32) {
        float4 v = hs[i];
        float4 w1 = t1[i];
        float4 w2 = t2[i];
        float4 m = make_float4(v.x + w1.x + w2.x, v.y + w1.y + w2.y,
                               v.z + w1.z + w2.z, v.w + w1.w + w2.w);
        asm volatile("red.global.add.v4.f32 [%0], {%1,%2,%3,%4};"
                     :: "l"(ag + i), "f"(m.x), "f"(m.y), "f"(m.z), "f"(m.w)
                     : "memory");
    }
}

// ---------------------------------------------------------------------------
// SGEMM: C[M,N] = A[M,K] @ B[K,N] + bias, optional ReLU.
// 128x128 block tile, BK=8, 8x8 per-thread micro-tile, 256 threads.
// ---------------------------------------------------------------------------
#define BM 128
#define BN 128
#define BK 8
#define TM 8
#define TN 8

__global__ void __launch_bounds__(256)
k_sgemm(const float* __restrict__ A, const float* __restrict__ B,
        const float* __restrict__ bias, float* __restrict__ C,
        int M, int N, int K, int doRelu)
{
    __shared__ float As[BK][BM];
    __shared__ float Bs[BK][BN];

    const int tid     = threadIdx.x;
    const int rowBase = blockIdx.y * BM;
    const int colBase = blockIdx.x * BN;

    // A tile load mapping: 128 rows x 8 cols = 256 float4
    const int aRow = tid >> 1;          // 0..127
    const int aCol = (tid & 1) * 4;     // 0 or 4
    // B tile load mapping: 8 rows x 128 cols = 256 float4
    const int bRow = tid >> 5;          // 0..7
    const int bCol = (tid & 31) * 4;    // 0..124

    const int tx = tid & 15;            // 0..15
    const int ty = tid >> 4;            // 0..15

    float acc[TM][TN];
#pragma unroll
    for (int i = 0; i < TM; i++)
#pragma unroll
        for (int j = 0; j < TN; j++) acc[i][j] = 0.0f;

    float ra[TM], rb[TN];

    for (int k0 = 0; k0 < K; k0 += BK) {
        // load A tile (transposed into As[k][m])
        float4 av = make_float4(0.f, 0.f, 0.f, 0.f);
        {
            int gr = rowBase + aRow;
            int gc = k0 + aCol;
            if (gr < M && gc < K)
                av = *reinterpret_cast<const float4*>(A + (size_t)gr * K + gc);
        }
        As[aCol + 0][aRow] = av.x;
        As[aCol + 1][aRow] = av.y;
        As[aCol + 2][aRow] = av.z;
        As[aCol + 3][aRow] = av.w;
        // load B tile
        float4 bv = make_float4(0.f, 0.f, 0.f, 0.f);
        {
            int gk = k0 + bRow;
            int gn = colBase + bCol;
            if (gk < K && gn < N)
                bv = *reinterpret_cast<const float4*>(B + (size_t)gk * N + gn);
        }
        *reinterpret_cast<float4*>(&Bs[bRow][bCol]) = bv;
        __syncthreads();

#pragma unroll
        for (int k = 0; k < BK; k++) {
            *reinterpret_cast<float4*>(&ra[0]) = *reinterpret_cast<float4*>(&As[k][ty * TM]);
            *reinterpret_cast<float4*>(&ra[4]) = *reinterpret_cast<float4*>(&As[k][ty * TM + 4]);
            *reinterpret_cast<float4*>(&rb[0]) = *reinterpret_cast<float4*>(&Bs[k][tx * TN]);
            *reinterpret_cast<float4*>(&rb[4]) = *reinterpret_cast<float4*>(&Bs[k][tx * TN + 4]);
#pragma unroll
            for (int i = 0; i < TM; i++)
#pragma unroll
                for (int j = 0; j < TN; j++)
                    acc[i][j] = fmaf(ra[i], rb[j], acc[i][j]);
        }
        __syncthreads();
    }

    // epilogue: bias + optional relu
#pragma unroll
    for (int i = 0; i < TM; i++) {
        int r = rowBase + ty * TM + i;
        if (r >= M) continue;
#pragma unroll
        for (int j = 0; j < TN; j += 4) {
            int c = colBase + tx * TN + j;
            if (c >= N) continue;            // N % 4 == 0, float4 granularity
            float4 o;
            o.x = acc[i][j + 0] + bias[c + 0];
            o.y = acc[i][j + 1] + bias[c + 1];
            o.z = acc[i][j + 2] + bias[c + 2];
            o.w = acc[i][j + 3] + bias[c + 3];
            if (doRelu) {
                o.x = fmaxf(o.x, 0.f); o.y = fmaxf(o.y, 0.f);
                o.z = fmaxf(o.z, 0.f); o.w = fmaxf(o.w, 0.f);
            }
            *reinterpret_cast<float4*>(C + (size_t)r * N + c) = o;
        }
    }
}

// ---------------------------------------------------------------------------
// BatchNorm: stats (per-channel sum & sumsq), finalize, apply (+ next agg init)
// ---------------------------------------------------------------------------
__global__ void k_zero600()
{
    int i = threadIdx.x;
    if (i < 600) g_stat[i] = 0.0f;
}

__global__ void k_bnstats(int n)
{
    int c = threadIdx.x;             // blockDim.x = 320, active c < 300
    if (c >= DD) return;
    int r0 = blockIdx.x * 128;
    int r1 = r0 + 128;
    if (r1 > n) r1 = n;
    float s = 0.f, q = 0.f;
    for (int r = r0; r < r1; r++) {
        float v = g_h2[(size_t)r * DD + c];
        s += v;
        q += v * v;
    }
    atomicAdd(&g_stat[c], s);
    atomicAdd(&g_stat[DD + c], q);
}

__global__ void k_bnfin(const float* __restrict__ gamma,
                        const float* __restrict__ beta, float invn)
{
    int c = threadIdx.x;
    if (c >= DD) return;
    float mean = g_stat[c] * invn;
    float var  = g_stat[DD + c] * invn - mean * mean;
    float a = gamma[c] * rsqrtf(var + 1e-5f);
    g_bnA[c] = a;
    g_bnB[c] = beta[c] - mean * a;
}

__global__ void k_bnapply(float4* __restrict__ outH,
                          float4* __restrict__ outAgg,
                          const float4* __restrict__ c1,
                          const float4* __restrict__ c2,
                          int n, int doRelu)
{
    int idx = blockIdx.x * blockDim.x + threadIdx.x;
    if (idx >= n * DD4) return;
    int j = idx % DD4;
    float4 v = reinterpret_cast<const float4*>(g_h2)[idx];
    float4 A = reinterpret_cast<const float4*>(g_bnA)[j];
    float4 B = reinterpret_cast<const float4*>(g_bnB)[j];
    float4 o = make_float4(fmaf(A.x, v.x, B.x), fmaf(A.y, v.y, B.y),
                           fmaf(A.z, v.z, B.z), fmaf(A.w, v.w, B.w));
    if (doRelu) {
        o.x = fmaxf(o.x, 0.f); o.y = fmaxf(o.y, 0.f);
        o.z = fmaxf(o.z, 0.f); o.w = fmaxf(o.w, 0.f);
    }
    outH[idx] = o;
    if (outAgg != nullptr) {
        float4 cc1 = c1[j];
        float4 cc2 = c2[j];
        outAgg[idx] = make_float4(o.x + cc1.x + cc2.x, o.y + cc1.y + cc2.y,
                                  o.z + cc1.z + cc2.z, o.w + cc1.w + cc2.w);
    }
}

// ---------------------------------------------------------------------------
// Host launcher
// ---------------------------------------------------------------------------
extern "C" void kernel_launch(void* const* d_in, const int* in_sizes, int n_in,
                              void* d_out, int out_size)
{
    const int*   x     = (const int*)  d_in[0];   // [N,2]
    const int*   ei    = (const int*)  d_in[1];   // [2,E]
    const int*   ea    = (const int*)  d_in[2];   // [E,2]
    const float* xe1   = (const float*)d_in[3];   // [121,300]
    const float* xe2   = (const float*)d_in[4];   // [11,300]
    const float* ee1   = (const float*)d_in[5];   // [5,7,300]
    const float* ee2   = (const float*)d_in[6];   // [5,3,300]
    const float* w1    = (const float*)d_in[7];   // [5,300,600]
    const float* b1    = (const float*)d_in[8];   // [5,600]
    const float* w2    = (const float*)d_in[9];   // [5,600,300]
    const float* b2    = (const float*)d_in[10];  // [5,300]
    const float* gamma = (const float*)d_in[11];  // [5,300]
    const float* beta  = (const float*)d_in[12];  // [5,300]

    const int N = in_sizes[0] / 2;
    const int E = in_sizes[1] / 2;

    float *h, *agg, *h1, *h2;
    cudaGetSymbolAddress((void**)&h,   g_h);
    cudaGetSymbolAddress((void**)&agg, g_agg);
    cudaGetSymbolAddress((void**)&h1,  g_h1);
    cudaGetSymbolAddress((void**)&h2,  g_h2);

    const int ewBlocks = (N * DD4 + 255) / 256;   // elementwise grid
    const int scBlocks = (E * 32 + 255) / 256;    // warp-per-edge grid

    // embed + layer-0 agg init (self-loop edge emb: ea0=4, ea1=0)
    k_embed_init<<<ewBlocks, 256>>>(
        x,
        (const float4*)xe1, (const float4*)xe2,
        (const float4*)(ee1 + 4 * DD),   // edge_emb1[0][4]
        (const float4*)(ee2),            // edge_emb2[0][0]
        N);

    for (int l = 0; l < NL; l++) {
        const float* ee1l = ee1 + (size_t)l * 7 * DD;
        const float* ee2l = ee2 + (size_t)l * 3 * DD;

        k_scatter<<<scBlocks, 256>>>(ei, ea, ee1l, ee2l, E);

        // h1 = relu(agg @ W1 + b1)   [N,600]
        {
            dim3 grid((600 + BN - 1) / BN, (N + BM - 1) / BM);
            k_sgemm<<<grid, 256>>>(agg, w1 + (size_t)l * DD * 600,
                                   b1 + (size_t)l * 600, h1,
                                   N, 600, DD, 1);
        }

        k_zero600<<<1, 640>>>();

        // h2 = h1 @ W2 + b2          [N,300]
        {
            dim3 grid((DD + BN - 1) / BN, (N + BM - 1) / BM);
            k_sgemm<<<grid, 256>>>(h1, w2 + (size_t)l * 600 * DD,
                                   b2 + (size_t)l * DD, h2,
                                   N, DD, 600, 0);
        }

        k_bnstats<<<(N + 127) / 128, 320>>>(N);
        k_bnfin<<<1, 320>>>(gamma + (size_t)l * DD, beta + (size_t)l * DD,
                            1.0f / (float)N);

        const bool last = (l == NL - 1);
        const float* ce1 = last ? ee1 : (ee1 + (size_t)(l + 1) * 7 * DD + 4 * DD);
        const float* ce2 = last ? ee2 : (ee2 + (size_t)(l + 1) * 3 * DD);
        k_bnapply<<<ewBlocks, 256>>>(
            last ? (float4*)d_out : (float4*)h,
            last ? (float4*)nullptr : (float4*)agg,
            (const float4*)ce1, (const float4*)ce2,
            N, last ? 0 : 1);
    }
}

// round 5
// speedup vs baseline: 2.0645x; 2.0638x over previous
#include <cuda_runtime.h>
#include <cuda_bf16.h>
#include <cstdint>

// ---------------------------------------------------------------------------
// GIN GNN, 5 layers, D=300, N=100000 nodes, E=200000 edges.
// GEMMs: warp-level mma.sync bf16 (3-way hi/lo split, fp32 accumulate).
// (tcgen05 is unavailable: harness PTX target is sm_103 without the 'a'.)
// ---------------------------------------------------------------------------

#define DD   300
#define DD4  75
#define NL   5

__device__ __align__(16) float g_h  [100000 * 300];
__device__ __align__(16) float g_agg[100000 * 300];
__device__ __align__(16) float g_h2 [100000 * 300];
__device__ __align__(16) float g_stat[600];
__device__ __align__(16) float g_bnA[300];
__device__ __align__(16) float g_bnB[300];

// bf16 hi/lo activation buffers
__device__ __align__(16) __nv_bfloat16 g_aggh[100000 * 320];
__device__ __align__(16) __nv_bfloat16 g_aggl[100000 * 320];
__device__ __align__(16) __nv_bfloat16 g_h1h [100000 * 640];
__device__ __align__(16) __nv_bfloat16 g_h1l [100000 * 640];

// Prepacked weights: bf16 hi/lo, transposed to [n][k], padded.
// B1: [5][2][640 n][320 k]   (w1: K=300->320, N=600->640)
// B2: [5][2][384 n][640 k]   (w2: K=600->640, N=300->384)
__device__ __align__(16) __nv_bfloat16 g_B1[5 * 2 * 640 * 320];
__device__ __align__(16) __nv_bfloat16 g_B2[5 * 2 * 384 * 640];

// ---------------------------------------------------------------------------
__device__ __forceinline__ uint32_t smem_u32(const void* p) {
    uint32_t a;
    asm("{ .reg .u64 t; cvta.to.shared.u64 t, %1; cvt.u32.u64 %0, t; }"
        : "=r"(a) : "l"(p));
    return a;
}

#define SWZ(off) ((off) ^ (((off) >> 3) & 0x70))

#define CP_ASYNC16(saddr, gaddr, sz) \
    asm volatile("cp.async.cg.shared.global [%0], [%1], 16, %2;" \
                 :: "r"(saddr), "l"(gaddr), "r"(sz) : "memory")
#define CP_COMMIT() asm volatile("cp.async.commit_group;" ::: "memory")
#define CP_WAIT1()  asm volatile("cp.async.wait_group 1;" ::: "memory")
#define CP_WAIT0()  asm volatile("cp.async.wait_group 0;" ::: "memory")

#define LDMX4(r0, r1, r2, r3, addr) \
    asm volatile("ldmatrix.sync.aligned.m8n8.x4.shared.b16 {%0,%1,%2,%3}, [%4];" \
                 : "=r"(r0), "=r"(r1), "=r"(r2), "=r"(r3) : "r"(addr))

#define MMA16816(c0, c1, c2, c3, a0, a1, a2, a3, b0, b1) \
    asm volatile("mma.sync.aligned.m16n8k16.row.col.f32.bf16.bf16.f32 " \
                 "{%0,%1,%2,%3}, {%4,%5,%6,%7}, {%8,%9}, {%0,%1,%2,%3};" \
                 : "+f"(c0), "+f"(c1), "+f"(c2), "+f"(c3) \
                 : "r"(a0), "r"(a1), "r"(a2), "r"(a3), "r"(b0), "r"(b1))

// smem tile offsets within one buffer (each tile 128 rows x 128B = 16KB)
#define A_HI 0
#define A_LO 16384
#define B_HI 32768
#define B_LO 49152
#define BUF_SZ 65536
#define DSMEM_SZ (2 * BUF_SZ + 1024)

// ---------------------------------------------------------------------------
// bf16-split GEMM: C[M,Ntrue] = (Ah+Al)[M,Kpad] @ (Bh+Bl)^T[Kpad,Npad] + bias
// mode 0: C -> Cf fp32, no relu.   mode 1: relu, write bf16 hi/lo to Ch/Cl
//         (row stride Npad), padding cols [Ntrue,Npad) written as zero.
// ---------------------------------------------------------------------------
__global__ void __launch_bounds__(256)
k_mmagemm(const __nv_bfloat16* __restrict__ Ah,
          const __nv_bfloat16* __restrict__ Al,
          const __nv_bfloat16* __restrict__ Bp,
          const float* __restrict__ bias,
          float* __restrict__ Cf,
          __nv_bfloat16* __restrict__ Ch, __nv_bfloat16* __restrict__ Cl,
          int M, int Ntrue, int Kpad, int Npad, int mode)
{
    extern __shared__ char dsm[];
    const uint32_t smb = (smem_u32(dsm) + 1023u) & ~1023u;

    const int tid  = threadIdx.x;
    const int wid  = tid >> 5;
    const int lane = tid & 31;
    const int m0 = blockIdx.y * 128;
    const int n0 = blockIdx.x * 128;
    const int nchunks = Kpad >> 6;

    const int am = (wid & 1) * 64;    // warp M offset in tile
    const int bn = (wid >> 1) * 32;   // warp N offset in tile

    const __nv_bfloat16* Bl_ = Bp + (size_t)Npad * Kpad;

    // loader indexing: 1024 16B-transfers per 16KB tile, 4 per thread
    const int lrow = tid >> 1;                 // used below per t
    (void)lrow;

    float acc[4][4][4];
#pragma unroll
    for (int i = 0; i < 4; i++)
#pragma unroll
        for (int j = 0; j < 4; j++)
#pragma unroll
            for (int q = 0; q < 4; q++) acc[i][j][q] = 0.0f;

    // ---- async tile loader for chunk c into buffer (c&1) ----
    auto load_chunk = [&](int c) {
        const uint32_t base = smb + (c & 1) * BUF_SZ;
        const int k0 = c << 6;
#pragma unroll
        for (int t = 0; t < 4; t++) {
            int idx = t * 256 + tid;           // 0..1023
            int row = idx >> 3;
            int c16 = idx & 7;
            uint32_t soff = SWZ((uint32_t)(row * 128 + c16 * 16));
            // A (guard rows)
            int gr = m0 + row;
            uint32_t asz = (gr < M) ? 16u : 0u;
            const char* ga = (const char*)(Ah + (size_t)gr * Kpad + k0 + c16 * 8);
            const char* gl = (const char*)(Al + (size_t)gr * Kpad + k0 + c16 * 8);
            CP_ASYNC16(base + A_HI + soff, ga, asz);
            CP_ASYNC16(base + A_LO + soff, gl, asz);
            // B (rows always < Npad)
            const char* gbh = (const char*)(Bp  + (size_t)(n0 + row) * Kpad + k0 + c16 * 8);
            const char* gbl = (const char*)(Bl_ + (size_t)(n0 + row) * Kpad + k0 + c16 * 8);
            CP_ASYNC16(base + B_HI + soff, gbh, 16u);
            CP_ASYNC16(base + B_LO + soff, gbl, 16u);
        }
    };

    load_chunk(0);
    CP_COMMIT();

    // ldmatrix lane addressing constants
    const int grp = lane >> 3;        // 0..3
    const int rim = lane & 7;         // row in 8x8 matrix
    const int radd = (grp & 1) * 8;
    const int cadd = (grp >> 1) * 16;

    for (int c = 0; c < nchunks; c++) {
        if (c + 1 < nchunks) {
            load_chunk(c + 1);
            CP_COMMIT();
            CP_WAIT1();
        } else {
            CP_WAIT0();
        }
        __syncthreads();

        const uint32_t base = smb + (c & 1) * BUF_SZ;
#pragma unroll
        for (int seg = 0; seg < 3; seg++) {
            const uint32_t abase = base + (seg == 1 ? A_LO : A_HI);
            const uint32_t bbase = base + (seg == 2 ? B_LO : B_HI);
#pragma unroll
            for (int k16 = 0; k16 < 4; k16++) {
                const int kb = k16 * 32;
                uint32_t a[4][4];
#pragma unroll
                for (int i = 0; i < 4; i++) {
                    uint32_t off = (uint32_t)((am + i * 16 + radd + rim) * 128 + kb + cadd);
                    LDMX4(a[i][0], a[i][1], a[i][2], a[i][3], abase + SWZ(off));
                }
                uint32_t b[4][2];
#pragma unroll
                for (int j = 0; j < 2; j++) {
                    uint32_t r0, r1, r2, r3;
                    uint32_t off = (uint32_t)((bn + j * 16 + radd + rim) * 128 + kb + cadd);
                    LDMX4(r0, r1, r2, r3, bbase + SWZ(off));
                    b[j * 2 + 0][0] = r0; b[j * 2 + 0][1] = r2;
                    b[j * 2 + 1][0] = r1; b[j * 2 + 1][1] = r3;
                }
#pragma unroll
                for (int i = 0; i < 4; i++)
#pragma unroll
                    for (int jj = 0; jj < 4; jj++)
                        MMA16816(acc[i][jj][0], acc[i][jj][1], acc[i][jj][2], acc[i][jj][3],
                                 a[i][0], a[i][1], a[i][2], a[i][3],
                                 b[jj][0], b[jj][1]);
            }
        }
        __syncthreads();
    }

    // ---- epilogue ----
    const int qr = lane >> 2;          // 0..7
    const int qp = (lane & 3) * 2;     // 0,2,4,6
#pragma unroll
    for (int i = 0; i < 4; i++) {
        int r0 = m0 + am + i * 16 + qr;
        int r1 = r0 + 8;
#pragma unroll
        for (int jj = 0; jj < 4; jj++) {
            int col = n0 + bn + jj * 8 + qp;
            float bx = (col < Ntrue) ? bias[col] : 0.0f;
            float by = (col + 1 < Ntrue) ? bias[col + 1] : 0.0f;
            float x0 = acc[i][jj][0] + bx, y0 = acc[i][jj][1] + by;
            float x1 = acc[i][jj][2] + bx, y1 = acc[i][jj][3] + by;
            if (mode == 1) {
                x0 = fmaxf(x0, 0.f); y0 = fmaxf(y0, 0.f);
                x1 = fmaxf(x1, 0.f); y1 = fmaxf(y1, 0.f);
                if (col >= Ntrue) { x0 = y0 = x1 = y1 = 0.f; }
                else if (col + 1 >= Ntrue) { y0 = y1 = 0.f; }
                // pack hi/lo bf16 pairs
                __nv_bfloat16 hx0 = __float2bfloat16_rn(x0);
                __nv_bfloat16 hy0 = __float2bfloat16_rn(y0);
                __nv_bfloat16 hx1 = __float2bfloat16_rn(x1);
                __nv_bfloat16 hy1 = __float2bfloat16_rn(y1);
                uint32_t hp0 = ((uint32_t)__bfloat16_as_ushort(hy0) << 16) | __bfloat16_as_ushort(hx0);
                uint32_t hp1 = ((uint32_t)__bfloat16_as_ushort(hy1) << 16) | __bfloat16_as_ushort(hx1);
                __nv_bfloat16 lx0 = __float2bfloat16_rn(x0 - __bfloat162float(hx0));
                __nv_bfloat16 ly0 = __float2bfloat16_rn(y0 - __bfloat162float(hy0));
                __nv_bfloat16 lx1 = __float2bfloat16_rn(x1 - __bfloat162float(hx1));
                __nv_bfloat16 ly1 = __float2bfloat16_rn(y1 - __bfloat162float(hy1));
                uint32_t lp0 = ((uint32_t)__bfloat16_as_ushort(ly0) << 16) | __bfloat16_as_ushort(lx0);
                uint32_t lp1 = ((uint32_t)__bfloat16_as_ushort(ly1) << 16) | __bfloat16_as_ushort(lx1);
                if (r0 < M) {
                    *(uint32_t*)((char*)Ch + ((size_t)r0 * Npad + col) * 2) = hp0;
                    *(uint32_t*)((char*)Cl + ((size_t)r0 * Npad + col) * 2) = lp0;
                }
                if (r1 < M) {
                    *(uint32_t*)((char*)Ch + ((size_t)r1 * Npad + col) * 2) = hp1;
                    *(uint32_t*)((char*)Cl + ((size_t)r1 * Npad + col) * 2) = lp1;
                }
            } else {
                if (col < Ntrue) {
                    if (r0 < M)
                        *(float2*)(Cf + (size_t)r0 * Ntrue + col) = make_float2(x0, y0);
                    if (r1 < M)
                        *(float2*)(Cf + (size_t)r1 * Ntrue + col) = make_float2(x1, y1);
                }
            }
        }
    }
}

// ---------------------------------------------------------------------------
// Weight prepack: transpose + pad + bf16 hi/lo split
// ---------------------------------------------------------------------------
__global__ void k_pack1(const float* __restrict__ w1)
{
    int idx = blockIdx.x * 256 + threadIdx.x;       // 5*640*320
    if (idx >= 5 * 640 * 320) return;
    int k = idx % 320;
    int n = (idx / 320) % 640;
    int l = idx / (320 * 640);
    float v = (n < 600 && k < 300)
        ? w1[(size_t)l * 300 * 600 + (size_t)k * 600 + n] : 0.f;
    __nv_bfloat16 h = __float2bfloat16_rn(v);
    __nv_bfloat16 lo = __float2bfloat16_rn(v - __bfloat162float(h));
    g_B1[((size_t)(l * 2 + 0) * 640 + n) * 320 + k] = h;
    g_B1[((size_t)(l * 2 + 1) * 640 + n) * 320 + k] = lo;
}

__global__ void k_pack2(const float* __restrict__ w2)
{
    int idx = blockIdx.x * 256 + threadIdx.x;       // 5*384*640
    if (idx >= 5 * 384 * 640) return;
    int k = idx % 640;
    int n = (idx / 640) % 384;
    int l = idx / (640 * 384);
    float v = (n < 300 && k < 600)
        ? w2[(size_t)l * 600 * 300 + (size_t)k * 300 + n] : 0.f;
    __nv_bfloat16 h = __float2bfloat16_rn(v);
    __nv_bfloat16 lo = __float2bfloat16_rn(v - __bfloat162float(h));
    g_B2[((size_t)(l * 2 + 0) * 384 + n) * 640 + k] = h;
    g_B2[((size_t)(l * 2 + 1) * 384 + n) * 640 + k] = lo;
}

// ---------------------------------------------------------------------------
// agg fp32 -> bf16 hi/lo, padded to 320 cols
// ---------------------------------------------------------------------------
__global__ void k_conv_agg(int n)
{
    int idx = blockIdx.x * blockDim.x + threadIdx.x;   // n*80 (uint2 = 4 bf16)
    if (idx >= n * 80) return;
    int i = idx / 80;
    int j = idx - i * 80;
    float4 v = make_float4(0.f, 0.f, 0.f, 0.f);
    if (j < 75) v = reinterpret_cast<const float4*>(g_agg)[i * 75 + j];
    __nv_bfloat16 h0 = __float2bfloat16_rn(v.x);
    __nv_bfloat16 h1 = __float2bfloat16_rn(v.y);
    __nv_bfloat16 h2 = __float2bfloat16_rn(v.z);
    __nv_bfloat16 h3 = __float2bfloat16_rn(v.w);
    uint2 hp, lp;
    hp.x = ((uint32_t)__bfloat16_as_ushort(h1) << 16) | __bfloat16_as_ushort(h0);
    hp.y = ((uint32_t)__bfloat16_as_ushort(h3) << 16) | __bfloat16_as_ushort(h2);
    __nv_bfloat16 l0 = __float2bfloat16_rn(v.x - __bfloat162float(h0));
    __nv_bfloat16 l1 = __float2bfloat16_rn(v.y - __bfloat162float(h1));
    __nv_bfloat16 l2 = __float2bfloat16_rn(v.z - __bfloat162float(h2));
    __nv_bfloat16 l3 = __float2bfloat16_rn(v.w - __bfloat162float(h3));
    lp.x = ((uint32_t)__bfloat16_as_ushort(l1) << 16) | __bfloat16_as_ushort(l0);
    lp.y = ((uint32_t)__bfloat16_as_ushort(l3) << 16) | __bfloat16_as_ushort(l2);
    reinterpret_cast<uint2*>(g_aggh)[idx] = hp;
    reinterpret_cast<uint2*>(g_aggl)[idx] = lp;
}

// ---------------------------------------------------------------------------
// Embedding + layer-0 agg init
// ---------------------------------------------------------------------------
__global__ void k_embed_init(const int* __restrict__ x,
                             const float4* __restrict__ e1,
                             const float4* __restrict__ e2,
                             const float4* __restrict__ c1,
                             const float4* __restrict__ c2,
                             int n)
{
    int idx = blockIdx.x * blockDim.x + threadIdx.x;
    if (idx >= n * DD4) return;
    int i = idx / DD4;
    int j = idx - i * DD4;
    int a0 = x[2 * i];
    int a1 = x[2 * i + 1];
    float4 v1 = e1[a0 * DD4 + j];
    float4 v2 = e2[a1 * DD4 + j];
    float4 h = make_float4(v1.x + v2.x, v1.y + v2.y, v1.z + v2.z, v1.w + v2.w);
    reinterpret_cast<float4*>(g_h)[idx] = h;
    float4 cc1 = c1[j];
    float4 cc2 = c2[j];
    reinterpret_cast<float4*>(g_agg)[idx] =
        make_float4(h.x + cc1.x + cc2.x, h.y + cc1.y + cc2.y,
                    h.z + cc1.z + cc2.z, h.w + cc1.w + cc2.w);
}

// ---------------------------------------------------------------------------
// Edge scatter: warp per edge, red.global.add.v4.f32
// ---------------------------------------------------------------------------
__global__ void k_scatter(const int* __restrict__ ei,
                          const int* __restrict__ ea,
                          const float* __restrict__ ee1,
                          const float* __restrict__ ee2,
                          int E)
{
    int gw   = (blockIdx.x * blockDim.x + threadIdx.x) >> 5;
    int lane = threadIdx.x & 31;
    if (gw >= E) return;
    int src = ei[gw];
    int dst = ei[E + gw];
    int a0  = ea[2 * gw];
    int a1  = ea[2 * gw + 1];
    const float4* hs = reinterpret_cast<const float4*>(g_h) + (size_t)src * DD4;
    const float4* t1 = reinterpret_cast<const float4*>(ee1) + a0 * DD4;
    const float4* t2 = reinterpret_cast<const float4*>(ee2) + a1 * DD4;
    float4*       ag = reinterpret_cast<float4*>(g_agg) + (size_t)dst * DD4;
    for (int i = lane; i < DD4; i += 32) {
        float4 v = hs[i];
        float4 w1 = t1[i];
        float4 w2 = t2[i];
        float4 m = make_float4(v.x + w1.x + w2.x, v.y + w1.y + w2.y,
                               v.z + w1.z + w2.z, v.w + w1.w + w2.w);
        asm volatile("red.global.add.v4.f32 [%0], {%1,%2,%3,%4};"
                     :: "l"(ag + i), "f"(m.x), "f"(m.y), "f"(m.z), "f"(m.w)
                     : "memory");
    }
}

// ---------------------------------------------------------------------------
// BatchNorm pieces
// ---------------------------------------------------------------------------
__global__ void k_zero600()
{
    int i = threadIdx.x;
    if (i < 600) g_stat[i] = 0.0f;
}

__global__ void k_bnstats(int n)
{
    int c = threadIdx.x;
    if (c >= DD) return;
    int r0 = blockIdx.x * 128;
    int r1 = r0 + 128;
    if (r1 > n) r1 = n;
    float s = 0.f, q = 0.f;
    for (int r = r0; r < r1; r++) {
        float v = g_h2[(size_t)r * DD + c];
        s += v;
        q += v * v;
    }
    atomicAdd(&g_stat[c], s);
    atomicAdd(&g_stat[DD + c], q);
}

__global__ void k_bnfin(const float* __restrict__ gamma,
                        const float* __restrict__ beta, float invn)
{
    int c = threadIdx.x;
    if (c >= DD) return;
    float mean = g_stat[c] * invn;
    float var  = g_stat[DD + c] * invn - mean * mean;
    float a = gamma[c] * rsqrtf(var + 1e-5f);
    g_bnA[c] = a;
    g_bnB[c] = beta[c] - mean * a;
}

__global__ void k_bnapply(float4* __restrict__ outH,
                          float4* __restrict__ outAgg,
                          const float4* __restrict__ c1,
                          const float4* __restrict__ c2,
                          int n, int doRelu)
{
    int idx = blockIdx.x * blockDim.x + threadIdx.x;
    if (idx >= n * DD4) return;
    int j = idx % DD4;
    float4 v = reinterpret_cast<const float4*>(g_h2)[idx];
    float4 A = reinterpret_cast<const float4*>(g_bnA)[j];
    float4 B = reinterpret_cast<const float4*>(g_bnB)[j];
    float4 o = make_float4(fmaf(A.x, v.x, B.x), fmaf(A.y, v.y, B.y),
                           fmaf(A.z, v.z, B.z), fmaf(A.w, v.w, B.w));
    if (doRelu) {
        o.x = fmaxf(o.x, 0.f); o.y = fmaxf(o.y, 0.f);
        o.z = fmaxf(o.z, 0.f); o.w = fmaxf(o.w, 0.f);
    }
    outH[idx] = o;
    if (outAgg != nullptr) {
        float4 cc1 = c1[j];
        float4 cc2 = c2[j];
        outAgg[idx] = make_float4(o.x + cc1.x + cc2.x, o.y + cc1.y + cc2.y,
                                  o.z + cc1.z + cc2.z, o.w + cc1.w + cc2.w);
    }
}

// ---------------------------------------------------------------------------
// Host launcher
// ---------------------------------------------------------------------------
extern "C" void kernel_launch(void* const* d_in, const int* in_sizes, int n_in,
                              void* d_out, int out_size)
{
    const int*   x     = (const int*)  d_in[0];
    const int*   ei    = (const int*)  d_in[1];
    const int*   ea    = (const int*)  d_in[2];
    const float* xe1   = (const float*)d_in[3];
    const float* xe2   = (const float*)d_in[4];
    const float* ee1   = (const float*)d_in[5];
    const float* ee2   = (const float*)d_in[6];
    const float* w1    = (const float*)d_in[7];
    const float* b1    = (const float*)d_in[8];
    const float* w2    = (const float*)d_in[9];
    const float* b2    = (const float*)d_in[10];
    const float* gamma = (const float*)d_in[11];
    const float* beta  = (const float*)d_in[12];

    const int N = in_sizes[0] / 2;
    const int E = in_sizes[1] / 2;

    float *h, *agg, *h2;
    __nv_bfloat16 *B1, *B2, *aggh, *aggl, *h1h, *h1l;
    cudaGetSymbolAddress((void**)&h,    g_h);
    cudaGetSymbolAddress((void**)&agg,  g_agg);
    cudaGetSymbolAddress((void**)&h2,   g_h2);
    cudaGetSymbolAddress((void**)&B1,   g_B1);
    cudaGetSymbolAddress((void**)&B2,   g_B2);
    cudaGetSymbolAddress((void**)&aggh, g_aggh);
    cudaGetSymbolAddress((void**)&aggl, g_aggl);
    cudaGetSymbolAddress((void**)&h1h,  g_h1h);
    cudaGetSymbolAddress((void**)&h1l,  g_h1l);

    static bool attrDone = false;
    if (!attrDone) {
        cudaFuncSetAttribute(k_mmagemm,
                             cudaFuncAttributeMaxDynamicSharedMemorySize, DSMEM_SZ);
        attrDone = true;
    }

    const int ewBlocks = (N * DD4 + 255) / 256;
    const int scBlocks = (E * 32 + 255) / 256;
    const int cvBlocks = (N * 80 + 255) / 256;
    const int mtiles = (N + 127) / 128;

    k_pack1<<<(5 * 640 * 320 + 255) / 256, 256>>>(w1);
    k_pack2<<<(5 * 384 * 640 + 255) / 256, 256>>>(w2);

    k_embed_init<<<ewBlocks, 256>>>(
        x, (const float4*)xe1, (const float4*)xe2,
        (const float4*)(ee1 + 4 * DD), (const float4*)(ee2), N);

    for (int l = 0; l < NL; l++) {
        const float* ee1l = ee1 + (size_t)l * 7 * DD;
        const float* ee2l = ee2 + (size_t)l * 3 * DD;

        k_scatter<<<scBlocks, 256>>>(ei, ea, ee1l, ee2l, E);
        k_conv_agg<<<cvBlocks, 256>>>(N);

        // h1 = relu(agg @ W1 + b1) -> bf16 hi/lo [N,640]
        k_mmagemm<<<dim3(5, mtiles), 256, DSMEM_SZ>>>(
            aggh, aggl, B1 + (size_t)l * 2 * 640 * 320, b1 + (size_t)l * 600,
            nullptr, h1h, h1l,
            N, 600, 320, 640, 1);

        k_zero600<<<1, 640>>>();

        // h2 = h1 @ W2 + b2 -> fp32 [N,300]
        k_mmagemm<<<dim3(3, mtiles), 256, DSMEM_SZ>>>(
            h1h, h1l, B2 + (size_t)l * 2 * 384 * 640, b2 + (size_t)l * DD,
            h2, nullptr, nullptr,
            N, 300, 640, 384, 0);

        k_bnstats<<<(N + 127) / 128, 320>>>(N);
        k_bnfin<<<1, 320>>>(gamma + (size_t)l * DD, beta + (size_t)l * DD,
                            1.0f / (float)N);

        const bool last = (l == NL - 1);
        const float* ce1 = last ? ee1 : (ee1 + (size_t)(l + 1) * 7 * DD + 4 * DD);
        const float* ce2 = last ? ee2 : (ee2 + (size_t)(l + 1) * 3 * DD);
        k_bnapply<<<ewBlocks, 256>>>(
            last ? (float4*)d_out : (float4*)h,
            last ? (float4*)nullptr : (float4*)agg,
            (const float4*)ce1, (const float4*)ce2,
            N, last ? 0 : 1);
    }
}

// round 6
// speedup vs baseline: 2.0701x; 1.0027x over previous
#include <cuda_runtime.h>
#include <cuda_bf16.h>
#include <cstdint>

// ---------------------------------------------------------------------------
// GIN GNN, 5 layers, D=300, N=100000 nodes, E=200000 edges.
// GEMMs: warp-level mma.sync bf16 (3-way hi/lo split, fp32 accumulate).
// (tcgen05 is unavailable: harness PTX target is sm_103 without the 'a'.)
// ---------------------------------------------------------------------------

#define DD   300
#define DD4  75
#define NL   5

__device__ __align__(16) float g_h  [100000 * 300];
__device__ __align__(16) float g_agg[100000 * 300];
__device__ __align__(16) float g_h2 [100000 * 300];
__device__ __align__(16) float g_stat[600];
__device__ __align__(16) float g_bnA[300];
__device__ __align__(16) float g_bnB[300];

// bf16 hi/lo activation buffers
__device__ __align__(16) __nv_bfloat16 g_aggh[100000 * 320];
__device__ __align__(16) __nv_bfloat16 g_aggl[100000 * 320];
__device__ __align__(16) __nv_bfloat16 g_h1h [100000 * 640];
__device__ __align__(16) __nv_bfloat16 g_h1l [100000 * 640];

// Prepacked weights: bf16 hi/lo, transposed to [n][k], padded.
// B1: [5][2][640 n][320 k]   (w1: K=300->320, N=600->640)
// B2: [5][2][384 n][640 k]   (w2: K=600->640, N=300->384)
__device__ __align__(16) __nv_bfloat16 g_B1[5 * 2 * 640 * 320];
__device__ __align__(16) __nv_bfloat16 g_B2[5 * 2 * 384 * 640];

// ---------------------------------------------------------------------------
__device__ __forceinline__ uint32_t smem_u32(const void* p) {
    uint32_t a;
    asm("{ .reg .u64 t; cvta.to.shared.u64 t, %1; cvt.u32.u64 %0, t; }"
        : "=r"(a) : "l"(p));
    return a;
}

#define SWZ(off) ((off) ^ (((off) >> 3) & 0x70))

#define CP_ASYNC16(saddr, gaddr, sz) \
    asm volatile("cp.async.cg.shared.global [%0], [%1], 16, %2;" \
                 :: "r"(saddr), "l"(gaddr), "r"(sz) : "memory")
#define CP_COMMIT() asm volatile("cp.async.commit_group;" ::: "memory")
#define CP_WAIT1()  asm volatile("cp.async.wait_group 1;" ::: "memory")
#define CP_WAIT0()  asm volatile("cp.async.wait_group 0;" ::: "memory")

#define LDMX4(r0, r1, r2, r3, addr) \
    asm volatile("ldmatrix.sync.aligned.m8n8.x4.shared.b16 {%0,%1,%2,%3}, [%4];" \
                 : "=r"(r0), "=r"(r1), "=r"(r2), "=r"(r3) : "r"(addr))

#define MMA16816(c0, c1, c2, c3, a0, a1, a2, a3, b0, b1) \
    asm volatile("mma.sync.aligned.m16n8k16.row.col.f32.bf16.bf16.f32 " \
                 "{%0,%1,%2,%3}, {%4,%5,%6,%7}, {%8,%9}, {%0,%1,%2,%3};" \
                 : "+f"(c0), "+f"(c1), "+f"(c2), "+f"(c3) \
                 : "r"(a0), "r"(a1), "r"(a2), "r"(a3), "r"(b0), "r"(b1))

// smem tile offsets within one buffer (each tile 128 rows x 128B = 16KB)
#define A_HI 0
#define A_LO 16384
#define B_HI 32768
#define B_LO 49152
#define BUF_SZ 65536
#define DSMEM_SZ (2 * BUF_SZ + 1024)

// ---------------------------------------------------------------------------
// bf16-split GEMM: C[M,Ntrue] = (Ah+Al)[M,Kpad] @ (Bh+Bl)^T[Kpad,Npad] + bias
// mode 0: C -> Cf fp32, no relu.   mode 1: relu, write bf16 hi/lo to Ch/Cl
//         (row stride Npad), padding cols [Ntrue,Npad) written as zero.
// ---------------------------------------------------------------------------
__global__ void __launch_bounds__(256)
k_mmagemm(const __nv_bfloat16* __restrict__ Ah,
          const __nv_bfloat16* __restrict__ Al,
          const __nv_bfloat16* __restrict__ Bp,
          const float* __restrict__ bias,
          float* __restrict__ Cf,
          __nv_bfloat16* __restrict__ Ch, __nv_bfloat16* __restrict__ Cl,
          int M, int Ntrue, int Kpad, int Npad, int mode)
{
    extern __shared__ char dsm[];
    const uint32_t smb = (smem_u32(dsm) + 1023u) & ~1023u;

    const int tid  = threadIdx.x;
    const int wid  = tid >> 5;
    const int lane = tid & 31;
    const int m0 = blockIdx.y * 128;
    const int n0 = blockIdx.x * 128;
    const int nchunks = Kpad >> 6;

    const int am = (wid & 1) * 64;    // warp M offset in tile
    const int bn = (wid >> 1) * 32;   // warp N offset in tile

    const __nv_bfloat16* Bl_ = Bp + (size_t)Npad * Kpad;

    // loader indexing: 1024 16B-transfers per 16KB tile, 4 per thread
    const int lrow = tid >> 1;                 // used below per t
    (void)lrow;

    float acc[4][4][4];
#pragma unroll
    for (int i = 0; i < 4; i++)
#pragma unroll
        for (int j = 0; j < 4; j++)
#pragma unroll
            for (int q = 0; q < 4; q++) acc[i][j][q] = 0.0f;

    // ---- async tile loader for chunk c into buffer (c&1) ----
    auto load_chunk = [&](int c) {
        const uint32_t base = smb + (c & 1) * BUF_SZ;
        const int k0 = c << 6;
#pragma unroll
        for (int t = 0; t < 4; t++) {
            int idx = t * 256 + tid;           // 0..1023
            int row = idx >> 3;
            int c16 = idx & 7;
            uint32_t soff = SWZ((uint32_t)(row * 128 + c16 * 16));
            // A (guard rows)
            int gr = m0 + row;
            uint32_t asz = (gr < M) ? 16u : 0u;
            const char* ga = (const char*)(Ah + (size_t)gr * Kpad + k0 + c16 * 8);
            const char* gl = (const char*)(Al + (size_t)gr * Kpad + k0 + c16 * 8);
            CP_ASYNC16(base + A_HI + soff, ga, asz);
            CP_ASYNC16(base + A_LO + soff, gl, asz);
            // B (rows always < Npad)
            const char* gbh = (const char*)(Bp  + (size_t)(n0 + row) * Kpad + k0 + c16 * 8);
            const char* gbl = (const char*)(Bl_ + (size_t)(n0 + row) * Kpad + k0 + c16 * 8);
            CP_ASYNC16(base + B_HI + soff, gbh, 16u);
            CP_ASYNC16(base + B_LO + soff, gbl, 16u);
        }
    };

    load_chunk(0);
    CP_COMMIT();

    // ldmatrix lane addressing constants
    const int grp = lane >> 3;        // 0..3
    const int rim = lane & 7;         // row in 8x8 matrix
    const int radd = (grp & 1) * 8;
    const int cadd = (grp >> 1) * 16;

    for (int c = 0; c < nchunks; c++) {
        if (c + 1 < nchunks) {
            load_chunk(c + 1);
            CP_COMMIT();
            CP_WAIT1();
        } else {
            CP_WAIT0();
        }
        __syncthreads();

        const uint32_t base = smb + (c & 1) * BUF_SZ;
#pragma unroll
        for (int seg = 0; seg < 3; seg++) {
            const uint32_t abase = base + (seg == 1 ? A_LO : A_HI);
            const uint32_t bbase = base + (seg == 2 ? B_LO : B_HI);
#pragma unroll
            for (int k16 = 0; k16 < 4; k16++) {
                const int kb = k16 * 32;
                uint32_t a[4][4];
#pragma unroll
                for (int i = 0; i < 4; i++) {
                    uint32_t off = (uint32_t)((am + i * 16 + radd + rim) * 128 + kb + cadd);
                    LDMX4(a[i][0], a[i][1], a[i][2], a[i][3], abase + SWZ(off));
                }
                uint32_t b[4][2];
#pragma unroll
                for (int j = 0; j < 2; j++) {
                    uint32_t r0, r1, r2, r3;
                    uint32_t off = (uint32_t)((bn + j * 16 + radd + rim) * 128 + kb + cadd);
                    LDMX4(r0, r1, r2, r3, bbase + SWZ(off));
                    b[j * 2 + 0][0] = r0; b[j * 2 + 0][1] = r2;
                    b[j * 2 + 1][0] = r1; b[j * 2 + 1][1] = r3;
                }
#pragma unroll
                for (int i = 0; i < 4; i++)
#pragma unroll
                    for (int jj = 0; jj < 4; jj++)
                        MMA16816(acc[i][jj][0], acc[i][jj][1], acc[i][jj][2], acc[i][jj][3],
                                 a[i][0], a[i][1], a[i][2], a[i][3],
                                 b[jj][0], b[jj][1]);
            }
        }
        __syncthreads();
    }

    // ---- epilogue ----
    const int qr = lane >> 2;          // 0..7
    const int qp = (lane & 3) * 2;     // 0,2,4,6
#pragma unroll
    for (int i = 0; i < 4; i++) {
        int r0 = m0 + am + i * 16 + qr;
        int r1 = r0 + 8;
#pragma unroll
        for (int jj = 0; jj < 4; jj++) {
            int col = n0 + bn + jj * 8 + qp;
            float bx = (col < Ntrue) ? bias[col] : 0.0f;
            float by = (col + 1 < Ntrue) ? bias[col + 1] : 0.0f;
            float x0 = acc[i][jj][0] + bx, y0 = acc[i][jj][1] + by;
            float x1 = acc[i][jj][2] + bx, y1 = acc[i][jj][3] + by;
            if (mode == 1) {
                x0 = fmaxf(x0, 0.f); y0 = fmaxf(y0, 0.f);
                x1 = fmaxf(x1, 0.f); y1 = fmaxf(y1, 0.f);
                if (col >= Ntrue) { x0 = y0 = x1 = y1 = 0.f; }
                else if (col + 1 >= Ntrue) { y0 = y1 = 0.f; }
                // pack hi/lo bf16 pairs
                __nv_bfloat16 hx0 = __float2bfloat16_rn(x0);
                __nv_bfloat16 hy0 = __float2bfloat16_rn(y0);
                __nv_bfloat16 hx1 = __float2bfloat16_rn(x1);
                __nv_bfloat16 hy1 = __float2bfloat16_rn(y1);
                uint32_t hp0 = ((uint32_t)__bfloat16_as_ushort(hy0) << 16) | __bfloat16_as_ushort(hx0);
                uint32_t hp1 = ((uint32_t)__bfloat16_as_ushort(hy1) << 16) | __bfloat16_as_ushort(hx1);
                __nv_bfloat16 lx0 = __float2bfloat16_rn(x0 - __bfloat162float(hx0));
                __nv_bfloat16 ly0 = __float2bfloat16_rn(y0 - __bfloat162float(hy0));
                __nv_bfloat16 lx1 = __float2bfloat16_rn(x1 - __bfloat162float(hx1));
                __nv_bfloat16 ly1 = __float2bfloat16_rn(y1 - __bfloat162float(hy1));
                uint32_t lp0 = ((uint32_t)__bfloat16_as_ushort(ly0) << 16) | __bfloat16_as_ushort(lx0);
                uint32_t lp1 = ((uint32_t)__bfloat16_as_ushort(ly1) << 16) | __bfloat16_as_ushort(lx1);
                if (r0 < M) {
                    *(uint32_t*)((char*)Ch + ((size_t)r0 * Npad + col) * 2) = hp0;
                    *(uint32_t*)((char*)Cl + ((size_t)r0 * Npad + col) * 2) = lp0;
                }
                if (r1 < M) {
                    *(uint32_t*)((char*)Ch + ((size_t)r1 * Npad + col) * 2) = hp1;
                    *(uint32_t*)((char*)Cl + ((size_t)r1 * Npad + col) * 2) = lp1;
                }
            } else {
                if (col < Ntrue) {
                    if (r0 < M)
                        *(float2*)(Cf + (size_t)r0 * Ntrue + col) = make_float2(x0, y0);
                    if (r1 < M)
                        *(float2*)(Cf + (size_t)r1 * Ntrue + col) = make_float2(x1, y1);
                }
            }
        }
    }
}

// ---------------------------------------------------------------------------
// Weight prepack: transpose + pad + bf16 hi/lo split
// ---------------------------------------------------------------------------
__global__ void k_pack1(const float* __restrict__ w1)
{
    int idx = blockIdx.x * 256 + threadIdx.x;       // 5*640*320
    if (idx >= 5 * 640 * 320) return;
    int k = idx % 320;
    int n = (idx / 320) % 640;
    int l = idx / (320 * 640);
    float v = (n < 600 && k < 300)
        ? w1[(size_t)l * 300 * 600 + (size_t)k * 600 + n] : 0.f;
    __nv_bfloat16 h = __float2bfloat16_rn(v);
    __nv_bfloat16 lo = __float2bfloat16_rn(v - __bfloat162float(h));
    g_B1[((size_t)(l * 2 + 0) * 640 + n) * 320 + k] = h;
    g_B1[((size_t)(l * 2 + 1) * 640 + n) * 320 + k] = lo;
}

__global__ void k_pack2(const float* __restrict__ w2)
{
    int idx = blockIdx.x * 256 + threadIdx.x;       // 5*384*640
    if (idx >= 5 * 384 * 640) return;
    int k = idx % 640;
    int n = (idx / 640) % 384;
    int l = idx / (640 * 384);
    float v = (n < 300 && k < 600)
        ? w2[(size_t)l * 600 * 300 + (size_t)k * 300 + n] : 0.f;
    __nv_bfloat16 h = __float2bfloat16_rn(v);
    __nv_bfloat16 lo = __float2bfloat16_rn(v - __bfloat162float(h));
    g_B2[((size_t)(l * 2 + 0) * 384 + n) * 640 + k] = h;
    g_B2[((size_t)(l * 2 + 1) * 384 + n) * 640 + k] = lo;
}

// ---------------------------------------------------------------------------
// agg fp32 -> bf16 hi/lo, padded to 320 cols
// ---------------------------------------------------------------------------
__global__ void k_conv_agg(int n)
{
    int idx = blockIdx.x * blockDim.x + threadIdx.x;   // n*80 (uint2 = 4 bf16)
    if (idx >= n * 80) return;
    int i = idx / 80;
    int j = idx - i * 80;
    float4 v = make_float4(0.f, 0.f, 0.f, 0.f);
    if (j < 75) v = reinterpret_cast<const float4*>(g_agg)[i * 75 + j];
    __nv_bfloat16 h0 = __float2bfloat16_rn(v.x);
    __nv_bfloat16 h1 = __float2bfloat16_rn(v.y);
    __nv_bfloat16 h2 = __float2bfloat16_rn(v.z);
    __nv_bfloat16 h3 = __float2bfloat16_rn(v.w);
    uint2 hp, lp;
    hp.x = ((uint32_t)__bfloat16_as_ushort(h1) << 16) | __bfloat16_as_ushort(h0);
    hp.y = ((uint32_t)__bfloat16_as_ushort(h3) << 16) | __bfloat16_as_ushort(h2);
    __nv_bfloat16 l0 = __float2bfloat16_rn(v.x - __bfloat162float(h0));
    __nv_bfloat16 l1 = __float2bfloat16_rn(v.y - __bfloat162float(h1));
    __nv_bfloat16 l2 = __float2bfloat16_rn(v.z - __bfloat162float(h2));
    __nv_bfloat16 l3 = __float2bfloat16_rn(v.w - __bfloat162float(h3));
    lp.x = ((uint32_t)__bfloat16_as_ushort(l1) << 16) | __bfloat16_as_ushort(l0);
    lp.y = ((uint32_t)__bfloat16_as_ushort(l3) << 16) | __bfloat16_as_ushort(l2);
    reinterpret_cast<uint2*>(g_aggh)[idx] = hp;
    reinterpret_cast<uint2*>(g_aggl)[idx] = lp;
}

// ---------------------------------------------------------------------------
// Embedding + layer-0 agg init
// ---------------------------------------------------------------------------
__global__ void k_embed_init(const int* __restrict__ x,
                             const float4* __restrict__ e1,
                             const float4* __restrict__ e2,
                             const float4* __restrict__ c1,
                             const float4* __restrict__ c2,
                             int n)
{
    int idx = blockIdx.x * blockDim.x + threadIdx.x;
    if (idx >= n * DD4) return;
    int i = idx / DD4;
    int j = idx - i * DD4;
    int a0 = x[2 * i];
    int a1 = x[2 * i + 1];
    float4 v1 = e1[a0 * DD4 + j];
    float4 v2 = e2[a1 * DD4 + j];
    float4 h = make_float4(v1.x + v2.x, v1.y + v2.y, v1.z + v2.z, v1.w + v2.w);
    reinterpret_cast<float4*>(g_h)[idx] = h;
    float4 cc1 = c1[j];
    float4 cc2 = c2[j];
    reinterpret_cast<float4*>(g_agg)[idx] =
        make_float4(h.x + cc1.x + cc2.x, h.y + cc1.y + cc2.y,
                    h.z + cc1.z + cc2.z, h.w + cc1.w + cc2.w);
}

// ---------------------------------------------------------------------------
// Edge scatter: warp per edge, red.global.add.v4.f32
// ---------------------------------------------------------------------------
__global__ void k_scatter(const int* __restrict__ ei,
                          const int* __restrict__ ea,
                          const float* __restrict__ ee1,
                          const float* __restrict__ ee2,
                          int E)
{
    int gw   = (blockIdx.x * blockDim.x + threadIdx.x) >> 5;
    int lane = threadIdx.x & 31;
    if (gw >= E) return;
    int src = ei[gw];
    int dst = ei[E + gw];
    int a0  = ea[2 * gw];
    int a1  = ea[2 * gw + 1];
    const float4* hs = reinterpret_cast<const float4*>(g_h) + (size_t)src * DD4;
    const float4* t1 = reinterpret_cast<const float4*>(ee1) + a0 * DD4;
    const float4* t2 = reinterpret_cast<const float4*>(ee2) + a1 * DD4;
    float4*       ag = reinterpret_cast<float4*>(g_agg) + (size_t)dst * DD4;
    for (int i = lane; i < DD4; i += 32) {
        float4 v = hs[i];
        float4 w1 = t1[i];
        float4 w2 = t2[i];
        float4 m = make_float4(v.x + w1.x + w2.x, v.y + w1.y + w2.y,
                               v.z + w1.z + w2.z, v.w + w1.w + w2.w);
        asm volatile("red.global.add.v4.f32 [%0], {%1,%2,%3,%4};"
                     :: "l"(ag + i), "f"(m.x), "f"(m.y), "f"(m.z), "f"(m.w)
                     : "memory");
    }
}

// ---------------------------------------------------------------------------
// BatchNorm pieces
// ---------------------------------------------------------------------------
__global__ void k_zero600()
{
    int i = threadIdx.x;
    if (i < 600) g_stat[i] = 0.0f;
}

__global__ void k_bnstats(int n)
{
    int c = threadIdx.x;
    if (c >= DD) return;
    int r0 = blockIdx.x * 128;
    int r1 = r0 + 128;
    if (r1 > n) r1 = n;
    float s = 0.f, q = 0.f;
    for (int r = r0; r < r1; r++) {
        float v = g_h2[(size_t)r * DD + c];
        s += v;
        q += v * v;
    }
    atomicAdd(&g_stat[c], s);
    atomicAdd(&g_stat[DD + c], q);
}

__global__ void k_bnfin(const float* __restrict__ gamma,
                        const float* __restrict__ beta, float invn)
{
    int c = threadIdx.x;
    if (c >= DD) return;
    float mean = g_stat[c] * invn;
    float var  = g_stat[DD + c] * invn - mean * mean;
    float a = gamma[c] * rsqrtf(var + 1e-5f);
    g_bnA[c] = a;
    g_bnB[c] = beta[c] - mean * a;
}

__global__ void k_bnapply(float4* __restrict__ outH,
                          float4* __restrict__ outAgg,
                          const float4* __restrict__ c1,
                          const float4* __restrict__ c2,
                          int n, int doRelu)
{
    int idx = blockIdx.x * blockDim.x + threadIdx.x;
    if (idx >= n * DD4) return;
    int j = idx % DD4;
    float4 v = reinterpret_cast<const float4*>(g_h2)[idx];
    float4 A = reinterpret_cast<const float4*>(g_bnA)[j];
    float4 B = reinterpret_cast<const float4*>(g_bnB)[j];
    float4 o = make_float4(fmaf(A.x, v.x, B.x), fmaf(A.y, v.y, B.y),
                           fmaf(A.z, v.z, B.z), fmaf(A.w, v.w, B.w));
    if (doRelu) {
        o.x = fmaxf(o.x, 0.f); o.y = fmaxf(o.y, 0.f);
        o.z = fmaxf(o.z, 0.f); o.w = fmaxf(o.w, 0.f);
    }
    outH[idx] = o;
    if (outAgg != nullptr) {
        float4 cc1 = c1[j];
        float4 cc2 = c2[j];
        outAgg[idx] = make_float4(o.x + cc1.x + cc2.x, o.y + cc1.y + cc2.y,
                                  o.z + cc1.z + cc2.z, o.w + cc1.w + cc2.w);
    }
}

// ---------------------------------------------------------------------------
// Host launcher
// ---------------------------------------------------------------------------
extern "C" void kernel_launch(void* const* d_in, const int* in_sizes, int n_in,
                              void* d_out, int out_size)
{
    const int*   x     = (const int*)  d_in[0];
    const int*   ei    = (const int*)  d_in[1];
    const int*   ea    = (const int*)  d_in[2];
    const float* xe1   = (const float*)d_in[3];
    const float* xe2   = (const float*)d_in[4];
    const float* ee1   = (const float*)d_in[5];
    const float* ee2   = (const float*)d_in[6];
    const float* w1    = (const float*)d_in[7];
    const float* b1    = (const float*)d_in[8];
    const float* w2    = (const float*)d_in[9];
    const float* b2    = (const float*)d_in[10];
    const float* gamma = (const float*)d_in[11];
    const float* beta  = (const float*)d_in[12];

    const int N = in_sizes[0] / 2;
    const int E = in_sizes[1] / 2;

    float *h, *agg, *h2;
    __nv_bfloat16 *B1, *B2, *aggh, *aggl, *h1h, *h1l;
    cudaGetSymbolAddress((void**)&h,    g_h);
    cudaGetSymbolAddress((void**)&agg,  g_agg);
    cudaGetSymbolAddress((void**)&h2,   g_h2);
    cudaGetSymbolAddress((void**)&B1,   g_B1);
    cudaGetSymbolAddress((void**)&B2,   g_B2);
    cudaGetSymbolAddress((void**)&aggh, g_aggh);
    cudaGetSymbolAddress((void**)&aggl, g_aggl);
    cudaGetSymbolAddress((void**)&h1h,  g_h1h);
    cudaGetSymbolAddress((void**)&h1l,  g_h1l);

    static bool attrDone = false;
    if (!attrDone) {
        cudaFuncSetAttribute(k_mmagemm,
                             cudaFuncAttributeMaxDynamicSharedMemorySize, DSMEM_SZ);
        attrDone = true;
    }

    const int ewBlocks = (N * DD4 + 255) / 256;
    const int scBlocks = (E * 32 + 255) / 256;
    const int cvBlocks = (N * 80 + 255) / 256;
    const int mtiles = (N + 127) / 128;

    k_pack1<<<(5 * 640 * 320 + 255) / 256, 256>>>(w1);
    k_pack2<<<(5 * 384 * 640 + 255) / 256, 256>>>(w2);

    k_embed_init<<<ewBlocks, 256>>>(
        x, (const float4*)xe1, (const float4*)xe2,
        (const float4*)(ee1 + 4 * DD), (const float4*)(ee2), N);

    for (int l = 0; l < NL; l++) {
        const float* ee1l = ee1 + (size_t)l * 7 * DD;
        const float* ee2l = ee2 + (size_t)l * 3 * DD;

        k_scatter<<<scBlocks, 256>>>(ei, ea, ee1l, ee2l, E);
        k_conv_agg<<<cvBlocks, 256>>>(N);

        // h1 = relu(agg @ W1 + b1) -> bf16 hi/lo [N,640]
        k_mmagemm<<<dim3(5, mtiles), 256, DSMEM_SZ>>>(
            aggh, aggl, B1 + (size_t)l * 2 * 640 * 320, b1 + (size_t)l * 600,
            nullptr, h1h, h1l,
            N, 600, 320, 640, 1);

        k_zero600<<<1, 640>>>();

        // h2 = h1 @ W2 + b2 -> fp32 [N,300]
        k_mmagemm<<<dim3(3, mtiles), 256, DSMEM_SZ>>>(
            h1h, h1l, B2 + (size_t)l * 2 * 384 * 640, b2 + (size_t)l * DD,
            h2, nullptr, nullptr,
            N, 300, 640, 384, 0);

        k_bnstats<<<(N + 127) / 128, 320>>>(N);
        k_bnfin<<<1, 320>>>(gamma + (size_t)l * DD, beta + (size_t)l * DD,
                            1.0f / (float)N);

        const bool last = (l == NL - 1);
        const float* ce1 = last ? ee1 : (ee1 + (size_t)(l + 1) * 7 * DD + 4 * DD);
        const float* ce2 = last ? ee2 : (ee2 + (size_t)(l + 1) * 3 * DD);
        k_bnapply<<<ewBlocks, 256>>>(
            last ? (float4*)d_out : (float4*)h,
            last ? (float4*)nullptr : (float4*)agg,
            (const float4*)ce1, (const float4*)ce2,
            N, last ? 0 : 1);
    }
}